// round 3
// baseline (speedup 1.0000x reference)
#include <cuda_runtime.h>
#include <cuda_fp16.h>
#include <cuda_bf16.h>
#include <mma.h>
#include <stdint.h>

using namespace nvcuda;

#define T_ROWS   256
#define K_DIM    8192
#define M_DIM    8192
#define N_CODES  1024
#define GP_ELEMS 1816   // 227 * 8

// scratch (device globals: allocation-free per harness rules)
__device__ __half  g_gp[2048];                      // canonical fp16 codebook
__device__ __half  g_xh[T_ROWS * K_DIM];            // 4 MB
__device__ __half  g_W [(size_t)M_DIM * K_DIM];     // 128 MB
__device__ float   g_z [T_ROWS * M_DIM];            // 8 MB

// ---------------------------------------------------------------------------
// K0: normalize grid_part to fp16 regardless of delivered dtype.
// gp[0] == 0.5 deterministically -> first 32 bits identify the dtype:
//   f32: 0x3F000000   bf16 pair: 0x3F003F00   f16 pair: 0x38003800
// ---------------------------------------------------------------------------
__global__ void prep_gp_kernel(const void* __restrict__ gp_raw)
{
    const uint32_t w0 = *(const uint32_t*)gp_raw;
    const int i = threadIdx.x + blockIdx.x * blockDim.x;
    if (i >= GP_ELEMS) return;
    float v;
    if (w0 == 0x3F000000u) {                 // float32
        v = ((const float*)gp_raw)[i];
    } else if (w0 == 0x3F003F00u) {          // bfloat16
        v = __bfloat162float(((const __nv_bfloat16*)gp_raw)[i]);
    } else {                                 // float16
        v = __half2float(((const __half*)gp_raw)[i]);
    }
    g_gp[i] = __float2half(v);               // exact: values are k+0.5, k<4
}

// ---------------------------------------------------------------------------
// K1: x = SU*x ; FWHT(8192) ; /(sqrt(8192)*1024) ; fp16
// ---------------------------------------------------------------------------
__global__ void fwht_in_kernel(const float* __restrict__ x,
                               const float* __restrict__ SU)
{
    __shared__ float s[K_DIM];
    const int row = blockIdx.x;
    const float* xr = x + (size_t)row * K_DIM;
    for (int i = threadIdx.x; i < K_DIM; i += 256)
        s[i] = xr[i] * SU[i];
    __syncthreads();
    for (int h = 1; h < K_DIM; h <<= 1) {
        #pragma unroll 1
        for (int j = 0; j < 16; j++) {
            int i   = threadIdx.x + j * 256;          // 0..4095
            int idx = ((i & ~(h - 1)) << 1) | (i & (h - 1));
            float a = s[idx], b = s[idx + h];
            s[idx]     = a + b;
            s[idx + h] = a - b;
        }
        __syncthreads();
    }
    const float c = 1.0789593218788508e-05f;   // 1/(sqrt(8192)*1024)
    __half* o = g_xh + (size_t)row * K_DIM;
    for (int i = threadIdx.x; i < K_DIM; i += 256)
        o[i] = __float2half(s[i] * c);
}

// ---------------------------------------------------------------------------
// K2: dequant: one thread per Qidx -> 8 fp16 (sign-flip via fp16 sign bits)
// ---------------------------------------------------------------------------
__global__ void dequant_kernel(const int* __restrict__ Q)
{
    int i = blockIdx.x * blockDim.x + threadIdx.x;   // 0 .. 8388607
    int idx   = Q[i] + 32768;
    int flips = idx >> 8;
    const uint32_t* g = (const uint32_t*)(g_gp + (idx & 255) * 8);
    uint4 o;
    o.x = g[0] ^ (((flips & 1)  ? 0x8000u : 0u) | ((flips & 2)   ? 0x80000000u : 0u));
    o.y = g[1] ^ (((flips & 4)  ? 0x8000u : 0u) | ((flips & 8)   ? 0x80000000u : 0u));
    o.z = g[2] ^ (((flips & 16) ? 0x8000u : 0u) | ((flips & 32)  ? 0x80000000u : 0u));
    o.w = g[3] ^ (((flips & 64) ? 0x8000u : 0u) | ((flips & 128) ? 0x80000000u : 0u));
    ((uint4*)g_W)[i] = o;
}

// ---------------------------------------------------------------------------
// K3: z[t][i] = sum_k xh[t][k] * W[i][k]
// wmma fp16 x fp16 -> fp32; block 128x64x64, 8 warps (4x2), warp 32x32
// ---------------------------------------------------------------------------
#define BM 128
#define BN 64
#define BK 64
#define LDS 72

__global__ void __launch_bounds__(256, 2) gemm_kernel()
{
    __shared__ __half As[BM * LDS];
    __shared__ __half Bs[BN * LDS];

    const int m0 = blockIdx.y * BM;
    const int n0 = blockIdx.x * BN;
    const int tid = threadIdx.x;
    const int warpId = tid >> 5;
    const int warpM  = warpId & 3;
    const int warpN  = warpId >> 2;

    wmma::fragment<wmma::accumulator, 16, 16, 16, float> acc[2][2];
    #pragma unroll
    for (int i = 0; i < 2; i++)
        #pragma unroll
        for (int j = 0; j < 2; j++)
            wmma::fill_fragment(acc[i][j], 0.0f);

    for (int k0 = 0; k0 < K_DIM; k0 += BK) {
        #pragma unroll
        for (int it = 0; it < 4; it++) {
            int lin = tid + it * 256;
            int r = lin >> 3, c = (lin & 7) * 8;
            *(uint4*)&As[r * LDS + c] =
                *(const uint4*)&g_xh[(size_t)(m0 + r) * K_DIM + k0 + c];
        }
        #pragma unroll
        for (int it = 0; it < 2; it++) {
            int lin = tid + it * 256;
            int r = lin >> 3, c = (lin & 7) * 8;
            *(uint4*)&Bs[r * LDS + c] =
                *(const uint4*)&g_W[(size_t)(n0 + r) * K_DIM + k0 + c];
        }
        __syncthreads();

        #pragma unroll
        for (int kk = 0; kk < 4; kk++) {
            wmma::fragment<wmma::matrix_a, 16, 16, 16, __half, wmma::row_major> a[2];
            wmma::fragment<wmma::matrix_b, 16, 16, 16, __half, wmma::col_major> b[2];
            #pragma unroll
            for (int i = 0; i < 2; i++)
                wmma::load_matrix_sync(a[i], &As[(warpM * 32 + i * 16) * LDS + kk * 16], LDS);
            #pragma unroll
            for (int j = 0; j < 2; j++)
                wmma::load_matrix_sync(b[j], &Bs[(warpN * 32 + j * 16) * LDS + kk * 16], LDS);
            #pragma unroll
            for (int i = 0; i < 2; i++)
                #pragma unroll
                for (int j = 0; j < 2; j++)
                    wmma::mma_sync(acc[i][j], a[i], b[j], acc[i][j]);
        }
        __syncthreads();
    }

    #pragma unroll
    for (int i = 0; i < 2; i++)
        #pragma unroll
        for (int j = 0; j < 2; j++)
            wmma::store_matrix_sync(
                &g_z[(size_t)(m0 + warpM * 32 + i * 16) * M_DIM +
                     n0 + warpN * 32 + j * 16],
                acc[i][j], M_DIM, wmma::mem_row_major);
}

// ---------------------------------------------------------------------------
// K4: out = SV * fwht(z) * (Wscale*1024/sqrt(8192))
// ---------------------------------------------------------------------------
__global__ void fwht_out_kernel(const float* __restrict__ SV,
                                const float* __restrict__ Wscale,
                                float* __restrict__ out)
{
    __shared__ float s[M_DIM];
    const int row = blockIdx.x;
    const float* zr = g_z + (size_t)row * M_DIM;
    for (int i = threadIdx.x; i < M_DIM; i += 256)
        s[i] = zr[i];
    __syncthreads();
    for (int h = 1; h < M_DIM; h <<= 1) {
        #pragma unroll 1
        for (int j = 0; j < 16; j++) {
            int i   = threadIdx.x + j * 256;
            int idx = ((i & ~(h - 1)) << 1) | (i & (h - 1));
            float a = s[idx], b = s[idx + h];
            s[idx]     = a + b;
            s[idx + h] = a - b;
        }
        __syncthreads();
    }
    const float c = Wscale[0] * 11.313708498984761f;  // 1024/sqrt(8192)
    float* o = out + (size_t)row * M_DIM;
    for (int i = threadIdx.x; i < M_DIM; i += 256)
        o[i] = s[i] * c * SV[i];
}

// ---------------------------------------------------------------------------
extern "C" void kernel_launch(void* const* d_in, const int* in_sizes, int n_in,
                              void* d_out, int out_size)
{
    // Resolve inputs by element count (robust to metadata ordering).
    const float* x  = nullptr;  const int*   Q  = nullptr;
    const float* SU = nullptr;  const float* SV = nullptr;
    const float* Ws = nullptr;  const void*  gp = nullptr;
    for (int i = 0; i < n_in; i++) {
        int s = in_sizes[i];
        if      (s == T_ROWS * K_DIM)   x  = (const float*)d_in[i];
        else if (s == M_DIM * N_CODES)  Q  = (const int*)d_in[i];
        else if (s == 1)                Ws = (const float*)d_in[i];
        else if (s == K_DIM) { if (!SU) SU = (const float*)d_in[i];
                               else     SV = (const float*)d_in[i]; }
        else                            gp = d_in[i];
    }
    float* out = (float*)d_out;

    prep_gp_kernel<<<8, 256>>>(gp);
    fwht_in_kernel<<<T_ROWS, 256>>>(x, SU);
    dequant_kernel<<<(M_DIM * N_CODES) / 256, 256>>>(Q);
    dim3 grid(M_DIM / BN, T_ROWS / BM);
    gemm_kernel<<<grid, 256>>>();
    fwht_out_kernel<<<T_ROWS, 256>>>(SV, Ws, out);
}

// round 5
// speedup vs baseline: 1.2130x; 1.2130x over previous
#include <cuda_runtime.h>
#include <cuda_fp16.h>
#include <cuda_bf16.h>
#include <mma.h>
#include <stdint.h>

using namespace nvcuda;

#define T_ROWS   256
#define K_DIM    8192
#define M_DIM    8192
#define N_CODES  1024
#define GP_ELEMS 1816   // 227 * 8

// scratch (device globals: allocation-free per harness rules)
__device__ __half  g_gp[2048];               // canonical fp16 codebook
__device__ __half  g_xh[T_ROWS * K_DIM];     // 4 MB
__device__ float   g_z [T_ROWS * M_DIM];     // 8 MB

__device__ __forceinline__ uint32_t smem_u32(const void* p) {
    uint32_t a;
    asm("{ .reg .u64 t; cvta.to.shared.u64 t, %1; cvt.u32.u64 %0, t; }"
        : "=r"(a) : "l"(p));
    return a;
}
__device__ __forceinline__ void cp_async16(uint32_t dst, const void* src) {
    asm volatile("cp.async.cg.shared.global [%0], [%1], 16;" :: "r"(dst), "l"(src));
}

// ---------------------------------------------------------------------------
// K0: normalize grid_part to fp16 regardless of delivered dtype.
// gp[0] == 0.5: f32 -> 0x3F000000, bf16 pair -> 0x3F003F00, f16 pair -> 0x38003800
// ---------------------------------------------------------------------------
__global__ void prep_gp_kernel(const void* __restrict__ gp_raw)
{
    const uint32_t w0 = *(const uint32_t*)gp_raw;
    const int i = threadIdx.x + blockIdx.x * blockDim.x;
    if (i >= GP_ELEMS) return;
    float v;
    if (w0 == 0x3F000000u)        v = ((const float*)gp_raw)[i];
    else if (w0 == 0x3F003F00u)   v = __bfloat162float(((const __nv_bfloat16*)gp_raw)[i]);
    else                          v = __half2float(((const __half*)gp_raw)[i]);
    g_gp[i] = __float2half(v);
}

// ---------------------------------------------------------------------------
// K1: x = SU*x ; FWHT(8192) ; /(sqrt(8192)*1024) ; fp16
// ---------------------------------------------------------------------------
__global__ void fwht_in_kernel(const float* __restrict__ x,
                               const float* __restrict__ SU)
{
    __shared__ float s[K_DIM];
    const int row = blockIdx.x;
    const float* xr = x + (size_t)row * K_DIM;
    for (int i = threadIdx.x; i < K_DIM; i += 256)
        s[i] = xr[i] * SU[i];
    __syncthreads();
    for (int h = 1; h < K_DIM; h <<= 1) {
        #pragma unroll 1
        for (int j = 0; j < 16; j++) {
            int i   = threadIdx.x + j * 256;
            int idx = ((i & ~(h - 1)) << 1) | (i & (h - 1));
            float a = s[idx], b = s[idx + h];
            s[idx]     = a + b;
            s[idx + h] = a - b;
        }
        __syncthreads();
    }
    const float c = 1.0789593218788508e-05f;   // 1/(sqrt(8192)*1024)
    __half* o = g_xh + (size_t)row * K_DIM;
    for (int i = threadIdx.x; i < K_DIM; i += 256)
        o[i] = __float2half(s[i] * c);
}

// ---------------------------------------------------------------------------
// K3: fused dequant + wmma GEMM, 3-stage cp.async pipeline
// z[t][i] = sum_k xh[t][k] * W[i][k], W decoded on the fly.
// block 128(m) x 128(n), K-chunk 64; 8 warps as 4(m) x 2(n), warp tile 32x64
// ---------------------------------------------------------------------------
#define STAGES      3
#define NCHUNK      128            // 8192 / 64
#define BMT         128
#define BNT         128
#define LDSM        72             // 64 + 8 pad halves; 144B row stride
#define TILE_BYTES  (128 * LDSM * 2)           // 18432 per operand tile
#define STAGE_BYTES (2 * TILE_BYTES)           // A + B
#define SM_CB       0                           // codebook 227*16B
#define SM_STAGE    4096
#define SMEM_GEMM   (SM_STAGE + STAGES * STAGE_BYTES)   // 114688

__global__ void __launch_bounds__(256, 1) gemm_fused_kernel(const int* __restrict__ Q)
{
    extern __shared__ char smem[];
    const uint32_t sb = smem_u32(smem);
    const int tid = threadIdx.x;
    const int warpId = tid >> 5;
    const int warpM  = warpId & 3;       // 0..3 -> 32 m-rows
    const int warpN  = warpId >> 2;      // 0..1 -> 64 n-cols
    const int n0 = blockIdx.x * BNT;
    const int m0 = blockIdx.y * BMT;

    if (tid < 227)
        *(uint4*)(smem + SM_CB + tid * 16) = *(const uint4*)(g_gp + tid * 8);
    __syncthreads();

    // per-thread fill indices
    const int a_row = tid >> 1;                 // reuse tid>>3 pattern below for A
    const int q_row = tid >> 1;                 // B decode row 0..127
    const int q_j0  = (tid & 1) * 4;            // code offset 0 or 4
    const int4* qptr = (const int4*)(Q + (size_t)(n0 + q_row) * N_CODES + q_j0);

    wmma::fragment<wmma::accumulator, 16, 16, 16, float> acc[2][4];
    #pragma unroll
    for (int i = 0; i < 2; i++)
        #pragma unroll
        for (int j = 0; j < 4; j++)
            wmma::fill_fragment(acc[i][j], 0.0f);

    auto fill = [&](int c, int4 q) {
        const int s = c % STAGES;
        const uint32_t abase = sb + SM_STAGE + s * STAGE_BYTES;
        // A tile: 128 rows x 128B, cp.async
        #pragma unroll
        for (int u = 0; u < 4; u++) {
            int lin = tid + u * 256;            // 0..1023 16B units
            int row = lin >> 3, c16 = lin & 7;
            cp_async16(abase + row * 144 + c16 * 16,
                       g_xh + (size_t)(m0 + row) * K_DIM + c * 64 + c16 * 8);
        }
        // B tile: decode 4 codes -> 4 x 16B STS
        char* bb = smem + SM_STAGE + s * STAGE_BYTES + TILE_BYTES;
        const int qs[4] = {q.x, q.y, q.z, q.w};
        #pragma unroll
        for (int e = 0; e < 4; e++) {
            int idx = qs[e] + 32768;
            int fl  = idx >> 8;
            const uint32_t* cb = (const uint32_t*)(smem + SM_CB + (idx & 255) * 16);
            uint4 o;
            o.x = cb[0] ^ (((fl & 1)  ? 0x8000u : 0u) | ((fl & 2)   ? 0x80000000u : 0u));
            o.y = cb[1] ^ (((fl & 4)  ? 0x8000u : 0u) | ((fl & 8)   ? 0x80000000u : 0u));
            o.z = cb[2] ^ (((fl & 16) ? 0x8000u : 0u) | ((fl & 32)  ? 0x80000000u : 0u));
            o.w = cb[3] ^ (((fl & 64) ? 0x8000u : 0u) | ((fl & 128) ? 0x80000000u : 0u));
            *(uint4*)(bb + q_row * 144 + (q_j0 + e) * 16) = o;
        }
    };

    // prologue: chunks 0 and 1
    fill(0, qptr[0]);
    asm volatile("cp.async.commit_group;" ::: "memory");
    fill(1, qptr[2]);   // chunk c: codes start at c*8 -> int4 index c*2
    asm volatile("cp.async.commit_group;" ::: "memory");

    for (int i = 0; i < NCHUNK; i++) {
        int4 qn = {0, 0, 0, 0};
        if (i + 2 < NCHUNK) qn = qptr[(i + 2) * 2];   // prefetch Q for chunk i+2

        asm volatile("cp.async.wait_group 1;" ::: "memory");
        __syncthreads();

        const int s = i % STAGES;
        const __half* As = (const __half*)(smem + SM_STAGE + s * STAGE_BYTES);
        const __half* Bs = (const __half*)(smem + SM_STAGE + s * STAGE_BYTES + TILE_BYTES);
        #pragma unroll
        for (int kk = 0; kk < 4; kk++) {
            wmma::fragment<wmma::matrix_a, 16, 16, 16, __half, wmma::row_major> a[2];
            wmma::fragment<wmma::matrix_b, 16, 16, 16, __half, wmma::col_major> b[4];
            #pragma unroll
            for (int ii = 0; ii < 2; ii++)
                wmma::load_matrix_sync(a[ii], &As[(warpM * 32 + ii * 16) * LDSM + kk * 16], LDSM);
            #pragma unroll
            for (int jj = 0; jj < 4; jj++)
                wmma::load_matrix_sync(b[jj], &Bs[(warpN * 64 + jj * 16) * LDSM + kk * 16], LDSM);
            #pragma unroll
            for (int ii = 0; ii < 2; ii++)
                #pragma unroll
                for (int jj = 0; jj < 4; jj++)
                    wmma::mma_sync(acc[ii][jj], a[ii], b[jj], acc[ii][jj]);
        }
        __syncthreads();

        if (i + 2 < NCHUNK) fill(i + 2, qn);
        asm volatile("cp.async.commit_group;" ::: "memory");
    }

    #pragma unroll
    for (int ii = 0; ii < 2; ii++)
        #pragma unroll
        for (int jj = 0; jj < 4; jj++)
            wmma::store_matrix_sync(
                &g_z[(size_t)(m0 + warpM * 32 + ii * 16) * M_DIM +
                     n0 + warpN * 64 + jj * 16],
                acc[ii][jj], M_DIM, wmma::mem_row_major);
}

// ---------------------------------------------------------------------------
// K4: out = SV * fwht(z) * (Wscale*1024/sqrt(8192))
// ---------------------------------------------------------------------------
__global__ void fwht_out_kernel(const float* __restrict__ SV,
                                const float* __restrict__ Wscale,
                                float* __restrict__ out)
{
    __shared__ float s[M_DIM];
    const int row = blockIdx.x;
    const float* zr = g_z + (size_t)row * M_DIM;
    for (int i = threadIdx.x; i < M_DIM; i += 256)
        s[i] = zr[i];
    __syncthreads();
    for (int h = 1; h < M_DIM; h <<= 1) {
        #pragma unroll 1
        for (int j = 0; j < 16; j++) {
            int i   = threadIdx.x + j * 256;
            int idx = ((i & ~(h - 1)) << 1) | (i & (h - 1));
            float a = s[idx], b = s[idx + h];
            s[idx]     = a + b;
            s[idx + h] = a - b;
        }
        __syncthreads();
    }
    const float c = Wscale[0] * 11.313708498984761f;  // 1024/sqrt(8192)
    float* o = out + (size_t)row * M_DIM;
    for (int i = threadIdx.x; i < M_DIM; i += 256)
        o[i] = s[i] * c * SV[i];
}

// ---------------------------------------------------------------------------
extern "C" void kernel_launch(void* const* d_in, const int* in_sizes, int n_in,
                              void* d_out, int out_size)
{
    const float* x  = nullptr;  const int*   Q  = nullptr;
    const float* SU = nullptr;  const float* SV = nullptr;
    const float* Ws = nullptr;  const void*  gp = nullptr;
    for (int i = 0; i < n_in; i++) {
        int s = in_sizes[i];
        if      (s == T_ROWS * K_DIM)   x  = (const float*)d_in[i];
        else if (s == M_DIM * N_CODES)  Q  = (const int*)d_in[i];
        else if (s == 1)                Ws = (const float*)d_in[i];
        else if (s == K_DIM) { if (!SU) SU = (const float*)d_in[i];
                               else     SV = (const float*)d_in[i]; }
        else                            gp = d_in[i];
    }
    float* out = (float*)d_out;

    static bool smem_set = false;
    if (!smem_set) {
        cudaFuncSetAttribute(gemm_fused_kernel,
                             cudaFuncAttributeMaxDynamicSharedMemorySize, SMEM_GEMM);
        smem_set = true;
    }

    prep_gp_kernel<<<8, 256>>>(gp);
    fwht_in_kernel<<<T_ROWS, 256>>>(x, SU);
    dim3 grid(M_DIM / BNT, T_ROWS / BMT);
    gemm_fused_kernel<<<grid, 256, SMEM_GEMM>>>(Q);
    fwht_out_kernel<<<T_ROWS, 256>>>(SV, Ws, out);
}